// round 4
// baseline (speedup 1.0000x reference)
#include <cuda_runtime.h>
#include <math.h>
#include <float.h>

#define B_  128
#define T_  8
#define E_  52
#define S_  2048
#define R_  512
#define L_  4
#define KX_ 104          // 2*E
#define NJ_ 1536         // 3*R
#define PSPLIT 8
#define PCHUNK (S_/PSPLIT)

// ---- scratch (device globals: no allocation allowed) ----
__device__ float g_pool_part[PSPLIT * B_ * R_];   // 2 MB
__device__ float g_a[B_ * L_];
__device__ float g_X[B_ * KX_];
__device__ float g_Gi[B_ * NJ_];                  // X @ W_ih^T + b_ih
__device__ float g_Ghp[4 * B_ * NJ_];             // split-K partials of h @ W_hh^T
__device__ float g_h[B_ * R_];

__constant__ int c_remap[4] = {175, 176, 44, 173};

// ---------------- h_n -> g_h ----------------
__global__ void k_copy_h(const float* __restrict__ h_n) {
    int i = blockIdx.x * blockDim.x + threadIdx.x;
    if (i < B_ * R_) g_h[i] = h_n[i];
}

// ---------------- ragged max pool (split along S) ----------------
__global__ void k_pool(const float* __restrict__ enc, const int* __restrict__ elen) {
    int b = blockIdx.x;
    int c = blockIdx.y;
    int tid = threadIdx.x;               // 128 threads, each owns 4 consecutive r (float4)
    int s0 = c * PCHUNK;
    int s1 = min(s0 + PCHUNK, elen[b]);
    int n  = s1 - s0;

    const float4* p4 = reinterpret_cast<const float4*>(enc);
    int base = (b * S_ + s0) * (R_ / 4) + tid;

    float4 m0 = make_float4(-FLT_MAX, -FLT_MAX, -FLT_MAX, -FLT_MAX);
    float4 m1 = m0, m2 = m0, m3 = m0;

    int s = 0;
    for (; s + 4 <= n; s += 4) {
        float4 v0 = p4[base + (s + 0) * (R_ / 4)];
        float4 v1 = p4[base + (s + 1) * (R_ / 4)];
        float4 v2 = p4[base + (s + 2) * (R_ / 4)];
        float4 v3 = p4[base + (s + 3) * (R_ / 4)];
        m0.x = fmaxf(m0.x, v0.x); m0.y = fmaxf(m0.y, v0.y); m0.z = fmaxf(m0.z, v0.z); m0.w = fmaxf(m0.w, v0.w);
        m1.x = fmaxf(m1.x, v1.x); m1.y = fmaxf(m1.y, v1.y); m1.z = fmaxf(m1.z, v1.z); m1.w = fmaxf(m1.w, v1.w);
        m2.x = fmaxf(m2.x, v2.x); m2.y = fmaxf(m2.y, v2.y); m2.z = fmaxf(m2.z, v2.z); m2.w = fmaxf(m2.w, v2.w);
        m3.x = fmaxf(m3.x, v3.x); m3.y = fmaxf(m3.y, v3.y); m3.z = fmaxf(m3.z, v3.z); m3.w = fmaxf(m3.w, v3.w);
    }
    for (; s < n; s++) {
        float4 v0 = p4[base + s * (R_ / 4)];
        m0.x = fmaxf(m0.x, v0.x); m0.y = fmaxf(m0.y, v0.y); m0.z = fmaxf(m0.z, v0.z); m0.w = fmaxf(m0.w, v0.w);
    }
    m0.x = fmaxf(fmaxf(m0.x, m1.x), fmaxf(m2.x, m3.x));
    m0.y = fmaxf(fmaxf(m0.y, m1.y), fmaxf(m2.y, m3.y));
    m0.z = fmaxf(fmaxf(m0.z, m1.z), fmaxf(m2.z, m3.z));
    m0.w = fmaxf(fmaxf(m0.w, m1.w), fmaxf(m2.w, m3.w));

    reinterpret_cast<float4*>(g_pool_part)[(c * B_ + b) * (R_ / 4) + tid] = m0;
}

// ---------------- reduce partials + a = code_pool @ W_fc_pool^T ----------------
__global__ void k_reduce_a(const float* __restrict__ wfc) {
    __shared__ float scp[R_];
    int b = blockIdx.x, tid = threadIdx.x;   // 128 threads = 4 warps
    const float4* P4 = reinterpret_cast<const float4*>(g_pool_part);
    float4 m = P4[(0 * B_ + b) * (R_ / 4) + tid];
    #pragma unroll
    for (int c = 1; c < PSPLIT; c++) {
        float4 v = P4[(c * B_ + b) * (R_ / 4) + tid];
        m.x = fmaxf(m.x, v.x); m.y = fmaxf(m.y, v.y);
        m.z = fmaxf(m.z, v.z); m.w = fmaxf(m.w, v.w);
    }
    reinterpret_cast<float4*>(scp)[tid] = m;
    __syncthreads();

    int w = tid >> 5, lane = tid & 31;       // warp w computes l = w
    float sdot = 0.f;
    #pragma unroll
    for (int q = 0; q < 16; q++) {
        int k = lane + 32 * q;
        sdot += scp[k] * wfc[w * R_ + k];
    }
    #pragma unroll
    for (int o = 16; o; o >>= 1) sdot += __shfl_down_sync(0xffffffffu, sdot, o);
    if (lane == 0) g_a[b * L_ + w] = sdot;
}

// ---------------- per-step fused: GRU gates (t>0) -> bmi_h -> argmax -> X build -> outputs ----
__global__ void k_step(const float* __restrict__ feat, const float* __restrict__ labE,
                       const int* __restrict__ mask, const float* __restrict__ emb,
                       const float* __restrict__ wreg, const float* __restrict__ breg,
                       const float* __restrict__ bhh, float* __restrict__ out, int t)
{
    __shared__ float hs[R_];
    __shared__ float smp[16];
    __shared__ float sbh[L_];
    __shared__ int   s_ld;
    int b = blockIdx.x, tid = threadIdx.x;   // 512 threads

    if (t > 0) {
        // finish previous step's GRU cell
        float gi_r = g_Gi[b * NJ_ + tid];
        float gi_z = g_Gi[b * NJ_ + 512 + tid];
        float gi_n = g_Gi[b * NJ_ + 1024 + tid];
        float gh_r = bhh[tid], gh_z = bhh[512 + tid], gh_n = bhh[1024 + tid];
        #pragma unroll
        for (int p = 0; p < 4; p++) {
            const float* G = g_Ghp + p * (B_ * NJ_) + b * NJ_;
            gh_r += G[tid]; gh_z += G[512 + tid]; gh_n += G[1024 + tid];
        }
        float h_old = g_h[b * R_ + tid];
        float rg = 1.f / (1.f + expf(-(gi_r + gh_r)));
        float zg = 1.f / (1.f + expf(-(gi_z + gh_z)));
        float ng = tanhf(gi_n + rg * gh_n);
        float hn = (1.f - zg) * ng + zg * h_old;
        g_h[b * R_ + tid] = hn;
        hs[tid] = hn;
    } else {
        hs[tid] = g_h[b * R_ + tid];
    }
    __syncthreads();

    // bmi_h[l] = h . W_reg[l] + b_reg[l] + a[b][l]   (16 warps: l = w>>2, chunk = w&3)
    int w = tid >> 5, lane = tid & 31;
    int l = w >> 2, ch = w & 3;
    float sdot = 0.f;
    #pragma unroll
    for (int q = 0; q < 4; q++) {
        int k = ch * 128 + q * 32 + lane;
        sdot += hs[k] * wreg[l * R_ + k];
    }
    #pragma unroll
    for (int o = 16; o; o >>= 1) sdot += __shfl_down_sync(0xffffffffu, sdot, o);
    if (lane == 0) smp[w] = sdot;
    __syncthreads();

    if (tid < 4) {
        float bh = smp[tid * 4] + smp[tid * 4 + 1] + smp[tid * 4 + 2] + smp[tid * 4 + 3]
                 + breg[tid] + g_a[b * L_ + tid];
        sbh[tid] = bh;
        int ob = t * B_ + b;
        out[1024 + ob * 4 + tid] = 1.f / (1.f + expf(-bh));  // dec_prob
        out[5120 + ob * 4 + tid] = bh;                        // disc_input (raw logits)
    }
    __syncthreads();

    if (tid == 0) {
        float best = sbh[0]; int li = 0;
        #pragma unroll
        for (int i = 1; i < 4; i++) if (sbh[i] > best) { best = sbh[i]; li = i; }
        int ld = c_remap[li];
        s_ld = ld;
        int ob = t * B_ + b;
        out[ob]        = (float)li;   // dec_output
        out[9216 + ob] = (float)ld;   // kl_input
    }
    __syncthreads();

    // build X[b] = [feat_t(52) | bmi(52)]
    if (tid < E_) {
        g_X[b * KX_ + tid] = feat[(b * T_ + t) * E_ + tid];
    } else if (tid < 2 * E_) {
        int e = tid - E_;
        int m = mask[b * T_ + t];
        float v = m ? labE[(b * T_ + t) * E_ + e] : emb[s_ld * E_ + e];
        g_X[b * KX_ + E_ + e] = v;
    }
}

// ---------------- split-K GEMM:  Gi = X @ W_ih^T + b_ih  /  Ghp[c] = h_chunk @ W_hh_chunk^T ----
// grid (24 N-tiles of 64, 5 K-chunks), 128 threads, 8x8 micro-tiles
#define SM_AS_STRIDE 129
#define SM_WS_STRIDE 65
#define GEMM_SMEM_BYTES ((128 * SM_AS_STRIDE + 128 * SM_WS_STRIDE) * 4)

__global__ void k_gemm(const float* __restrict__ wih, const float* __restrict__ whh,
                       const float* __restrict__ bih)
{
    extern __shared__ float sm[];
    float* As = sm;                              // [128][129]
    float* Ws = sm + 128 * SM_AS_STRIDE;         // [K][65]  (transposed weight tile)

    int nt  = blockIdx.x;        // 0..23
    int chk = blockIdx.y;        // 0..4
    int tid = threadIdx.x;       // 128
    int j0  = nt * 64;

    int K;
    const float* Ag; int lda;
    const float* Wg; int ldw;
    if (chk == 0) { K = KX_; Ag = g_X;                lda = KX_; Wg = wih;                  ldw = KX_; }
    else          { K = 128; Ag = g_h + (chk-1)*128;  lda = R_;  Wg = whh + (chk-1)*128;    ldw = R_;  }

    // load A tile [128 x K]
    for (int idx = tid; idx < 128 * K; idx += 128) {
        int bb = idx / K, k = idx % K;
        As[bb * SM_AS_STRIDE + k] = Ag[bb * lda + k];
    }
    // load W tile transposed: Ws[k][jj], jj in [0,64)
    for (int idx = tid; idx < 64 * K; idx += 128) {
        int jj = idx / K, k = idx % K;
        Ws[k * SM_WS_STRIDE + jj] = Wg[(j0 + jj) * ldw + k];
    }
    __syncthreads();

    int tj = tid & 7, tb = tid >> 3;   // 16 x 8 thread grid; 8x8 outputs each
    float acc[8][8];
    #pragma unroll
    for (int i = 0; i < 8; i++)
        #pragma unroll
        for (int u = 0; u < 8; u++) acc[i][u] = 0.f;

    for (int k = 0; k < K; k++) {
        float a[8], wv[8];
        #pragma unroll
        for (int i = 0; i < 8; i++) a[i]  = As[(tb * 8 + i) * SM_AS_STRIDE + k];
        #pragma unroll
        for (int u = 0; u < 8; u++) wv[u] = Ws[k * SM_WS_STRIDE + tj * 8 + u];
        #pragma unroll
        for (int i = 0; i < 8; i++)
            #pragma unroll
            for (int u = 0; u < 8; u++) acc[i][u] = fmaf(a[i], wv[u], acc[i][u]);
    }

    if (chk == 0) {
        #pragma unroll
        for (int i = 0; i < 8; i++) {
            int bb = tb * 8 + i;
            int jb = j0 + tj * 8;
            #pragma unroll
            for (int u = 0; u < 8; u++)
                g_Gi[bb * NJ_ + jb + u] = acc[i][u] + bih[jb + u];
        }
    } else {
        float* G = g_Ghp + (chk - 1) * (B_ * NJ_);
        #pragma unroll
        for (int i = 0; i < 8; i++) {
            int bb = tb * 8 + i;
            int jb = j0 + tj * 8;
            #pragma unroll
            for (int u = 0; u < 8; u++)
                G[bb * NJ_ + jb + u] = acc[i][u];
        }
    }
}

// ---------------- launch ----------------
extern "C" void kernel_launch(void* const* d_in, const int* in_sizes, int n_in,
                              void* d_out, int out_size) {
    (void)in_sizes; (void)n_in; (void)out_size;
    const float* feat = (const float*)d_in[0];
    const float* labE = (const float*)d_in[1];
    const float* enc  = (const float*)d_in[2];
    const float* h_n  = (const float*)d_in[3];
    const int*   mask = (const int*)d_in[4];
    const int*   elen = (const int*)d_in[5];
    const float* emb  = (const float*)d_in[6];
    const float* wfc  = (const float*)d_in[7];
    const float* wreg = (const float*)d_in[8];
    const float* breg = (const float*)d_in[9];
    const float* wih  = (const float*)d_in[10];
    const float* whh  = (const float*)d_in[11];
    const float* bih  = (const float*)d_in[12];
    const float* bhh  = (const float*)d_in[13];
    float* out = (float*)d_out;

    cudaFuncSetAttribute(k_gemm, cudaFuncAttributeMaxDynamicSharedMemorySize, GEMM_SMEM_BYTES);

    k_copy_h<<<(B_ * R_ + 255) / 256, 256>>>(h_n);
    k_pool<<<dim3(B_, PSPLIT), 128>>>(enc, elen);
    k_reduce_a<<<B_, 128>>>(wfc);

    for (int t = 0; t < T_; t++) {
        k_step<<<B_, 512>>>(feat, labE, mask, emb, wreg, breg, bhh, out, t);
        if (t < T_ - 1)
            k_gemm<<<dim3(24, 5), 128, GEMM_SMEM_BYTES>>>(wih, whh, bih);
    }
}

// round 5
// speedup vs baseline: 1.0218x; 1.0218x over previous
#include <cuda_runtime.h>
#include <math.h>
#include <float.h>

#define B_  128
#define T_  8
#define E_  52
#define S_  2048
#define R_  512
#define L_  4
#define KX_ 104          // 2*E
#define NJ_ 1536         // 3*R
#define PSPLIT 8
#define PCHUNK (S_/PSPLIT)

// ---- scratch (device globals: no allocation allowed) ----
__device__ float g_pool_part[PSPLIT * B_ * R_];   // 2 MB
__device__ float g_a[B_ * L_];
__device__ float g_X[B_ * KX_];
__device__ float g_Gi[B_ * NJ_];                  // X @ W_ih^T + b_ih
__device__ float g_Ghp[4 * B_ * NJ_];             // split-K partials of h @ W_hh^T
__device__ float g_h[B_ * R_];

__constant__ int c_remap[4] = {175, 176, 44, 173};

// ---------------- h_n -> g_h ----------------
__global__ void k_copy_h(const float* __restrict__ h_n) {
    int i = blockIdx.x * blockDim.x + threadIdx.x;
    if (i < B_ * R_) g_h[i] = h_n[i];
}

// ---------------- ragged max pool (split along S) ----------------
__global__ void k_pool(const float* __restrict__ enc, const int* __restrict__ elen) {
    int b = blockIdx.x;
    int c = blockIdx.y;
    int tid = threadIdx.x;               // 128 threads, each owns 4 consecutive r (float4)
    int s0 = c * PCHUNK;
    int s1 = min(s0 + PCHUNK, elen[b]);
    int n  = s1 - s0;

    const float4* p4 = reinterpret_cast<const float4*>(enc);
    int base = (b * S_ + s0) * (R_ / 4) + tid;

    float4 m0 = make_float4(-FLT_MAX, -FLT_MAX, -FLT_MAX, -FLT_MAX);
    float4 m1 = m0, m2 = m0, m3 = m0;

    int s = 0;
    for (; s + 4 <= n; s += 4) {
        float4 v0 = p4[base + (s + 0) * (R_ / 4)];
        float4 v1 = p4[base + (s + 1) * (R_ / 4)];
        float4 v2 = p4[base + (s + 2) * (R_ / 4)];
        float4 v3 = p4[base + (s + 3) * (R_ / 4)];
        m0.x = fmaxf(m0.x, v0.x); m0.y = fmaxf(m0.y, v0.y); m0.z = fmaxf(m0.z, v0.z); m0.w = fmaxf(m0.w, v0.w);
        m1.x = fmaxf(m1.x, v1.x); m1.y = fmaxf(m1.y, v1.y); m1.z = fmaxf(m1.z, v1.z); m1.w = fmaxf(m1.w, v1.w);
        m2.x = fmaxf(m2.x, v2.x); m2.y = fmaxf(m2.y, v2.y); m2.z = fmaxf(m2.z, v2.z); m2.w = fmaxf(m2.w, v2.w);
        m3.x = fmaxf(m3.x, v3.x); m3.y = fmaxf(m3.y, v3.y); m3.z = fmaxf(m3.z, v3.z); m3.w = fmaxf(m3.w, v3.w);
    }
    for (; s < n; s++) {
        float4 v0 = p4[base + s * (R_ / 4)];
        m0.x = fmaxf(m0.x, v0.x); m0.y = fmaxf(m0.y, v0.y); m0.z = fmaxf(m0.z, v0.z); m0.w = fmaxf(m0.w, v0.w);
    }
    m0.x = fmaxf(fmaxf(m0.x, m1.x), fmaxf(m2.x, m3.x));
    m0.y = fmaxf(fmaxf(m0.y, m1.y), fmaxf(m2.y, m3.y));
    m0.z = fmaxf(fmaxf(m0.z, m1.z), fmaxf(m2.z, m3.z));
    m0.w = fmaxf(fmaxf(m0.w, m1.w), fmaxf(m2.w, m3.w));

    reinterpret_cast<float4*>(g_pool_part)[(c * B_ + b) * (R_ / 4) + tid] = m0;
}

// ---------------- reduce partials + a = code_pool @ W_fc_pool^T ----------------
__global__ void k_reduce_a(const float* __restrict__ wfc) {
    __shared__ float scp[R_];
    int b = blockIdx.x, tid = threadIdx.x;   // 128 threads = 4 warps
    const float4* P4 = reinterpret_cast<const float4*>(g_pool_part);
    float4 m = P4[(0 * B_ + b) * (R_ / 4) + tid];
    #pragma unroll
    for (int c = 1; c < PSPLIT; c++) {
        float4 v = P4[(c * B_ + b) * (R_ / 4) + tid];
        m.x = fmaxf(m.x, v.x); m.y = fmaxf(m.y, v.y);
        m.z = fmaxf(m.z, v.z); m.w = fmaxf(m.w, v.w);
    }
    reinterpret_cast<float4*>(scp)[tid] = m;
    __syncthreads();

    int w = tid >> 5, lane = tid & 31;       // warp w computes l = w
    float sdot = 0.f;
    #pragma unroll
    for (int q = 0; q < 16; q++) {
        int k = lane + 32 * q;
        sdot += scp[k] * wfc[w * R_ + k];
    }
    #pragma unroll
    for (int o = 16; o; o >>= 1) sdot += __shfl_down_sync(0xffffffffu, sdot, o);
    if (lane == 0) g_a[b * L_ + w] = sdot;
}

// ---------------- per-step fused: GRU gates (t>0) -> bmi_h -> argmax -> X build -> outputs ----
__global__ void k_step(const float* __restrict__ feat, const float* __restrict__ labE,
                       const int* __restrict__ mask, const float* __restrict__ emb,
                       const float* __restrict__ wreg, const float* __restrict__ breg,
                       const float* __restrict__ bhh, float* __restrict__ out, int t)
{
    __shared__ float hs[R_];
    __shared__ float smp[16];
    __shared__ float sbh[L_];
    __shared__ int   s_ld;
    int b = blockIdx.x, tid = threadIdx.x;   // 512 threads

    if (t > 0) {
        // finish previous step's GRU cell
        float gi_r = g_Gi[b * NJ_ + tid];
        float gi_z = g_Gi[b * NJ_ + 512 + tid];
        float gi_n = g_Gi[b * NJ_ + 1024 + tid];
        float gh_r = bhh[tid], gh_z = bhh[512 + tid], gh_n = bhh[1024 + tid];
        #pragma unroll
        for (int p = 0; p < 4; p++) {
            const float* G = g_Ghp + p * (B_ * NJ_) + b * NJ_;
            gh_r += G[tid]; gh_z += G[512 + tid]; gh_n += G[1024 + tid];
        }
        float h_old = g_h[b * R_ + tid];
        float rg = 1.f / (1.f + expf(-(gi_r + gh_r)));
        float zg = 1.f / (1.f + expf(-(gi_z + gh_z)));
        float ng = tanhf(gi_n + rg * gh_n);
        float hn = (1.f - zg) * ng + zg * h_old;
        g_h[b * R_ + tid] = hn;
        hs[tid] = hn;
    } else {
        hs[tid] = g_h[b * R_ + tid];
    }
    __syncthreads();

    // bmi_h[l] = h . W_reg[l] + b_reg[l] + a[b][l]   (16 warps: l = w>>2, chunk = w&3)
    int w = tid >> 5, lane = tid & 31;
    int l = w >> 2, ch = w & 3;
    float sdot = 0.f;
    #pragma unroll
    for (int q = 0; q < 4; q++) {
        int k = ch * 128 + q * 32 + lane;
        sdot += hs[k] * wreg[l * R_ + k];
    }
    #pragma unroll
    for (int o = 16; o; o >>= 1) sdot += __shfl_down_sync(0xffffffffu, sdot, o);
    if (lane == 0) smp[w] = sdot;
    __syncthreads();

    if (tid < 4) {
        float bh = smp[tid * 4] + smp[tid * 4 + 1] + smp[tid * 4 + 2] + smp[tid * 4 + 3]
                 + breg[tid] + g_a[b * L_ + tid];
        sbh[tid] = bh;
        int ob = t * B_ + b;
        out[1024 + ob * 4 + tid] = 1.f / (1.f + expf(-bh));  // dec_prob
        out[5120 + ob * 4 + tid] = bh;                        // disc_input (raw logits)
    }
    __syncthreads();

    if (tid == 0) {
        float best = sbh[0]; int li = 0;
        #pragma unroll
        for (int i = 1; i < 4; i++) if (sbh[i] > best) { best = sbh[i]; li = i; }
        int ld = c_remap[li];
        s_ld = ld;
        int ob = t * B_ + b;
        out[ob]        = (float)li;   // dec_output
        out[9216 + ob] = (float)ld;   // kl_input
    }
    __syncthreads();

    // build X[b] = [feat_t(52) | bmi(52)]
    if (tid < E_) {
        g_X[b * KX_ + tid] = feat[(b * T_ + t) * E_ + tid];
    } else if (tid < 2 * E_) {
        int e = tid - E_;
        int m = mask[b * T_ + t];
        float v = m ? labE[(b * T_ + t) * E_ + e] : emb[s_ld * E_ + e];
        g_X[b * KX_ + E_ + e] = v;
    }
}

// ---------------- split-K GEMM:  Gi = X @ W_ih^T + b_ih  /  Ghp[c] = h_chunk @ W_hh_chunk^T ----
// grid (24 N-tiles of 64, 5 K-chunks), 128 threads, 8x8 micro-tiles
#define SM_AS_STRIDE 129
#define SM_WS_STRIDE 65
#define GEMM_SMEM_BYTES ((128 * SM_AS_STRIDE + 128 * SM_WS_STRIDE) * 4)

__global__ void k_gemm(const float* __restrict__ wih, const float* __restrict__ whh,
                       const float* __restrict__ bih)
{
    extern __shared__ float sm[];
    float* As = sm;                              // [128][129]
    float* Ws = sm + 128 * SM_AS_STRIDE;         // [K][65]  (transposed weight tile)

    int nt  = blockIdx.x;        // 0..23
    int chk = blockIdx.y;        // 0..4
    int tid = threadIdx.x;       // 128
    int j0  = nt * 64;

    int K;
    const float* Ag; int lda;
    const float* Wg; int ldw;
    if (chk == 0) { K = KX_; Ag = g_X;                lda = KX_; Wg = wih;                  ldw = KX_; }
    else          { K = 128; Ag = g_h + (chk-1)*128;  lda = R_;  Wg = whh + (chk-1)*128;    ldw = R_;  }

    // load A tile [128 x K]
    for (int idx = tid; idx < 128 * K; idx += 128) {
        int bb = idx / K, k = idx % K;
        As[bb * SM_AS_STRIDE + k] = Ag[bb * lda + k];
    }
    // load W tile transposed: Ws[k][jj], jj in [0,64)
    for (int idx = tid; idx < 64 * K; idx += 128) {
        int jj = idx / K, k = idx % K;
        Ws[k * SM_WS_STRIDE + jj] = Wg[(j0 + jj) * ldw + k];
    }
    __syncthreads();

    int tj = tid & 7, tb = tid >> 3;   // 16 x 8 thread grid; 8x8 outputs each
    float acc[8][8];
    #pragma unroll
    for (int i = 0; i < 8; i++)
        #pragma unroll
        for (int u = 0; u < 8; u++) acc[i][u] = 0.f;

    for (int k = 0; k < K; k++) {
        float a[8], wv[8];
        #pragma unroll
        for (int i = 0; i < 8; i++) a[i]  = As[(tb * 8 + i) * SM_AS_STRIDE + k];
        #pragma unroll
        for (int u = 0; u < 8; u++) wv[u] = Ws[k * SM_WS_STRIDE + tj * 8 + u];
        #pragma unroll
        for (int i = 0; i < 8; i++)
            #pragma unroll
            for (int u = 0; u < 8; u++) acc[i][u] = fmaf(a[i], wv[u], acc[i][u]);
    }

    if (chk == 0) {
        #pragma unroll
        for (int i = 0; i < 8; i++) {
            int bb = tb * 8 + i;
            int jb = j0 + tj * 8;
            #pragma unroll
            for (int u = 0; u < 8; u++)
                g_Gi[bb * NJ_ + jb + u] = acc[i][u] + bih[jb + u];
        }
    } else {
        float* G = g_Ghp + (chk - 1) * (B_ * NJ_);
        #pragma unroll
        for (int i = 0; i < 8; i++) {
            int bb = tb * 8 + i;
            int jb = j0 + tj * 8;
            #pragma unroll
            for (int u = 0; u < 8; u++)
                G[bb * NJ_ + jb + u] = acc[i][u];
        }
    }
}

// ---------------- launch ----------------
extern "C" void kernel_launch(void* const* d_in, const int* in_sizes, int n_in,
                              void* d_out, int out_size) {
    (void)in_sizes; (void)n_in; (void)out_size;
    const float* feat = (const float*)d_in[0];
    const float* labE = (const float*)d_in[1];
    const float* enc  = (const float*)d_in[2];
    const float* h_n  = (const float*)d_in[3];
    const int*   mask = (const int*)d_in[4];
    const int*   elen = (const int*)d_in[5];
    const float* emb  = (const float*)d_in[6];
    const float* wfc  = (const float*)d_in[7];
    const float* wreg = (const float*)d_in[8];
    const float* breg = (const float*)d_in[9];
    const float* wih  = (const float*)d_in[10];
    const float* whh  = (const float*)d_in[11];
    const float* bih  = (const float*)d_in[12];
    const float* bhh  = (const float*)d_in[13];
    float* out = (float*)d_out;

    cudaFuncSetAttribute(k_gemm, cudaFuncAttributeMaxDynamicSharedMemorySize, GEMM_SMEM_BYTES);

    k_copy_h<<<(B_ * R_ + 255) / 256, 256>>>(h_n);
    k_pool<<<dim3(B_, PSPLIT), 128>>>(enc, elen);
    k_reduce_a<<<B_, 128>>>(wfc);

    for (int t = 0; t < T_; t++) {
        k_step<<<B_, 512>>>(feat, labE, mask, emb, wreg, breg, bhh, out, t);
        if (t < T_ - 1)
            k_gemm<<<dim3(24, 5), 128, GEMM_SMEM_BYTES>>>(wih, whh, bih);
    }
}